// round 1
// baseline (speedup 1.0000x reference)
#include <cuda_runtime.h>
#include <math.h>

#define NFFT   384
#define TT     16              // transforms per block
#define ES     17              // padded element stride (floats) to dodge bank conflicts
#define HW     147456          // 384*384
#define NIMG   96              // 32 batch * 3 channels
#define NPIX   (NIMG*HW)
#define NCH    3
#define BLOCK  256
#define TILES  (NFFT/TT)       // 24
#define BUF    (NFFT*ES)       // 6528 floats per smem plane
#define SMEM_FLOATS (4*BUF + 2*NFFT)
#define SMEM_BYTES  (SMEM_FLOATS*4)
#define TWO_PI 6.283185307179586476925286766559

// ---------------- device scratch (no allocation allowed) ----------------
__device__ float2 g_spec[NPIX];        // 113 MB complex spectrum scratch
__device__ float  g_ampsum[NCH*HW];    // batch-summed amplitude
__device__ float  g_rsum[1];           // sum(running_amp) flag

// ---------------- butterflies ----------------
// S = +1 : exp(-i theta) (forward).  S = -1 : exp(+i theta) (inverse).
__device__ __forceinline__ void bfly8(float S,
    const float ar[8], const float ai[8], float br[8], float bi[8])
{
    const float c = 0.70710678118654752440f;
    // E = DFT4(a0,a2,a4,a6)
    float t0r=ar[0]+ar[4], t0i=ai[0]+ai[4];
    float t1r=ar[0]-ar[4], t1i=ai[0]-ai[4];
    float t2r=ar[2]+ar[6], t2i=ai[2]+ai[6];
    float t3r=ar[2]-ar[6], t3i=ai[2]-ai[6];
    float E0r=t0r+t2r, E0i=t0i+t2i;
    float E2r=t0r-t2r, E2i=t0i-t2i;
    float E1r=t1r+S*t3i, E1i=t1i-S*t3r;
    float E3r=t1r-S*t3i, E3i=t1i+S*t3r;
    // O = DFT4(a1,a3,a5,a7)
    float u0r=ar[1]+ar[5], u0i=ai[1]+ai[5];
    float u1r=ar[1]-ar[5], u1i=ai[1]-ai[5];
    float u2r=ar[3]+ar[7], u2i=ai[3]+ai[7];
    float u3r=ar[3]-ar[7], u3i=ai[3]-ai[7];
    float O0r=u0r+u2r, O0i=u0i+u2i;
    float O2r=u0r-u2r, O2i=u0i-u2i;
    float O1r=u1r+S*u3i, O1i=u1i-S*u3r;
    float O3r=u1r-S*u3i, O3i=u1i+S*u3r;
    // O1 *= W8^1 = c(1 - iS) ; O2 *= W8^2 = -iS ; O3 *= W8^3 = -c(1 + iS)
    float w1r =  c*(O1r + S*O1i), w1i =  c*(O1i - S*O1r);
    float w2r =  S*O2i,           w2i = -S*O2r;
    float w3r = -c*(O3r - S*O3i), w3i = -c*(O3i + S*O3r);
    br[0]=E0r+O0r; bi[0]=E0i+O0i;
    br[4]=E0r-O0r; bi[4]=E0i-O0i;
    br[1]=E1r+w1r; bi[1]=E1i+w1i;
    br[5]=E1r-w1r; bi[5]=E1i-w1i;
    br[2]=E2r+w2r; bi[2]=E2i+w2i;
    br[6]=E2r-w2r; bi[6]=E2i-w2i;
    br[3]=E3r+w3r; bi[3]=E3i+w3i;
    br[7]=E3r-w3r; bi[7]=E3i-w3i;
}

__device__ __forceinline__ void bfly6(float S,
    const float ar[6], const float ai[6], float br[6], float bi[6])
{
    const float s3 = 0.86602540378443864676f;
    // E = DFT3(a0,a2,a4)
    float t1r=ar[2]+ar[4], t1i=ai[2]+ai[4];
    float E0r=ar[0]+t1r,   E0i=ai[0]+t1i;
    float t2r=ar[0]-0.5f*t1r, t2i=ai[0]-0.5f*t1i;
    float t3r=s3*(ar[2]-ar[4]), t3i=s3*(ai[2]-ai[4]);
    float E1r=t2r+S*t3i, E1i=t2i-S*t3r;
    float E2r=t2r-S*t3i, E2i=t2i+S*t3r;
    // O = DFT3(a1,a3,a5)
    float v1r=ar[3]+ar[5], v1i=ai[3]+ai[5];
    float O0r=ar[1]+v1r,   O0i=ai[1]+v1i;
    float v2r=ar[1]-0.5f*v1r, v2i=ai[1]-0.5f*v1i;
    float v3r=s3*(ar[3]-ar[5]), v3i=s3*(ai[3]-ai[5]);
    float O1r=v2r+S*v3i, O1i=v2i-S*v3r;
    float O2r=v2r-S*v3i, O2i=v2i+S*v3r;
    // O1 *= W6^1 = 0.5 - iS*s3 ; O2 *= W6^2 = -0.5 - iS*s3
    float w1r =  0.5f*O1r + S*s3*O1i, w1i =  0.5f*O1i - S*s3*O1r;
    float w2r = -0.5f*O2r + S*s3*O2i, w2i = -0.5f*O2i - S*s3*O2r;
    br[0]=E0r+O0r; bi[0]=E0i+O0i;
    br[3]=E0r-O0r; bi[3]=E0i-O0i;
    br[1]=E1r+w1r; bi[1]=E1i+w1i;
    br[4]=E1r-w1r; bi[4]=E1i-w1i;
    br[2]=E2r+w2r; bi[2]=E2i+w2i;
    br[5]=E2r-w2r; bi[5]=E2i-w2i;
}

// ---------------- twiddle table : tw[k] = exp(-i*SGN*2*pi*k/384) ----------------
template<int SGN>
__device__ __forceinline__ void build_tw(float* twr, float* twi)
{
    for (int k = threadIdx.x; k < NFFT; k += BLOCK) {
        float sv, cv;
        sincosf((float)k * (float)(TWO_PI/384.0), &sv, &cv);
        twr[k] = cv;
        twi[k] = (SGN > 0) ? -sv : sv;
    }
}

// ---------------- 384-pt Stockham FFT, radices [8,8,6], 16 transforms/block ----------------
// Input in (reA,imA); output in natural order in (reB,imB).
template<int SGN>
__device__ __forceinline__ void fft384_tile(
    float* reA, float* imA, float* reB, float* imB,
    const float* __restrict__ twr, const float* __restrict__ twi)
{
    constexpr float S = (float)SGN;
    // ---- Stage 1: radix-8, s=1, A -> B ----
    for (int i = threadIdx.x; i < TT*48; i += BLOCK) {
        const int t = i & (TT-1);
        const int p = i >> 4;                 // 0..47
        float ar[8], ai[8], br[8], bi[8];
#pragma unroll
        for (int j = 0; j < 8; ++j) {
            const int e = p + 48*j;
            ar[j] = reA[e*ES + t]; ai[j] = imA[e*ES + t];
        }
        bfly8(S, ar, ai, br, bi);
#pragma unroll
        for (int j = 1; j < 8; ++j) {
            const int w = p*j;
            const float cr = twr[w], ci = twi[w];
            const float xr = br[j], xi = bi[j];
            br[j] = xr*cr - xi*ci;
            bi[j] = xr*ci + xi*cr;
        }
#pragma unroll
        for (int j = 0; j < 8; ++j) {
            const int e = 8*p + j;
            reB[e*ES + t] = br[j]; imB[e*ES + t] = bi[j];
        }
    }
    __syncthreads();
    // ---- Stage 2: radix-8, s=8, B -> A ----
    for (int i = threadIdx.x; i < TT*48; i += BLOCK) {
        const int t = i & (TT-1);
        const int u = i >> 4;                 // 0..47
        const int q = u & 7;
        const int p = u >> 3;                 // 0..5
        const int base = q + 8*p;
        float ar[8], ai[8], br[8], bi[8];
#pragma unroll
        for (int j = 0; j < 8; ++j) {
            const int e = base + 48*j;
            ar[j] = reB[e*ES + t]; ai[j] = imB[e*ES + t];
        }
        bfly8(S, ar, ai, br, bi);
#pragma unroll
        for (int j = 1; j < 8; ++j) {
            const int w = 8*p*j;
            const float cr = twr[w], ci = twi[w];
            const float xr = br[j], xi = bi[j];
            br[j] = xr*cr - xi*ci;
            bi[j] = xr*ci + xi*cr;
        }
#pragma unroll
        for (int j = 0; j < 8; ++j) {
            const int e = q + 64*p + 8*j;
            reA[e*ES + t] = br[j]; imA[e*ES + t] = bi[j];
        }
    }
    __syncthreads();
    // ---- Stage 3: radix-6, s=64, A -> B (all twiddles = 1) ----
    for (int i = threadIdx.x; i < TT*64; i += BLOCK) {
        const int t = i & (TT-1);
        const int q = i >> 4;                 // 0..63
        float ar[6], ai[6], br[6], bi[6];
#pragma unroll
        for (int j = 0; j < 6; ++j) {
            const int e = q + 64*j;
            ar[j] = reA[e*ES + t]; ai[j] = imA[e*ES + t];
        }
        bfly6(S, ar, ai, br, bi);
#pragma unroll
        for (int j = 0; j < 6; ++j) {
            const int e = q + 64*j;
            reB[e*ES + t] = br[j]; imB[e*ES + t] = bi[j];
        }
    }
    __syncthreads();
}

// ---------------- kernels ----------------
__global__ void __launch_bounds__(BLOCK) k_reduce(const float* __restrict__ a, int n)
{
    float s = 0.f;
    for (int i = blockIdx.x*BLOCK + threadIdx.x; i < n; i += gridDim.x*BLOCK)
        s += a[i];
#pragma unroll
    for (int o = 16; o > 0; o >>= 1) s += __shfl_down_sync(0xffffffffu, s, o);
    __shared__ float ws[BLOCK/32];
    if ((threadIdx.x & 31) == 0) ws[threadIdx.x >> 5] = s;
    __syncthreads();
    if (threadIdx.x < BLOCK/32) {
        s = ws[threadIdx.x];
#pragma unroll
        for (int o = BLOCK/64; o > 0; o >>= 1) s += __shfl_down_sync(0xffu, s, o);
        if (threadIdx.x == 0) atomicAdd(g_rsum, s);
    }
}

__global__ void __launch_bounds__(BLOCK) k_row_fwd(const float* __restrict__ x)
{
    extern __shared__ float sm[];
    float* reA = sm;         float* imA = sm + BUF;
    float* reB = sm + 2*BUF; float* imB = sm + 3*BUF;
    float* twr = sm + 4*BUF; float* twi = twr + NFFT;
    build_tw<1>(twr, twi);

    const int img = blockIdx.x / TILES;
    const int h0  = (blockIdx.x % TILES) * TT;
    const float* xp = x + (size_t)img*HW + (size_t)h0*NFFT;
    for (int idx = threadIdx.x; idx < TT*NFFT; idx += BLOCK) {
        const int w = idx % NFFT, r = idx / NFFT;
        reA[w*ES + r] = xp[idx];
        imA[w*ES + r] = 0.f;
    }
    __syncthreads();
    fft384_tile<1>(reA, imA, reB, imB, twr, twi);
    float2* sp = g_spec + (size_t)img*HW + (size_t)h0*NFFT;
    for (int idx = threadIdx.x; idx < TT*NFFT; idx += BLOCK) {
        const int w = idx % NFFT, r = idx / NFFT;
        sp[idx] = make_float2(reB[w*ES + r], imB[w*ES + r]);
    }
}

__global__ void __launch_bounds__(BLOCK) k_col_fwd()
{
    extern __shared__ float sm[];
    float* reA = sm;         float* imA = sm + BUF;
    float* reB = sm + 2*BUF; float* imB = sm + 3*BUF;
    float* twr = sm + 4*BUF; float* twi = twr + NFFT;
    build_tw<1>(twr, twi);

    const int img = blockIdx.x / TILES;
    const int w0  = (blockIdx.x % TILES) * TT;
    float2* sp = g_spec + (size_t)img*HW + w0;
    for (int idx = threadIdx.x; idx < TT*NFFT; idx += BLOCK) {
        const int c = idx & (TT-1), h = idx >> 4;
        float2 v = sp[(size_t)h*NFFT + c];
        reA[h*ES + c] = v.x; imA[h*ES + c] = v.y;
    }
    __syncthreads();
    fft384_tile<1>(reA, imA, reB, imB, twr, twi);
    const int ch = img % NCH;
    float* ab = g_ampsum + (size_t)ch*HW + w0;
    for (int idx = threadIdx.x; idx < TT*NFFT; idx += BLOCK) {
        const int c = idx & (TT-1), h = idx >> 4;
        const float re = reB[h*ES + c], im = imB[h*ES + c];
        sp[(size_t)h*NFFT + c] = make_float2(re, im);
        atomicAdd(&ab[h*NFFT + c], sqrtf(re*re + im*im));
    }
}

__global__ void __launch_bounds__(BLOCK) k_col_inv(const float* __restrict__ running)
{
    extern __shared__ float sm[];
    float* reA = sm;         float* imA = sm + BUF;
    float* reB = sm + 2*BUF; float* imB = sm + 3*BUF;
    float* twr = sm + 4*BUF; float* twi = twr + NFFT;
    build_tw<-1>(twr, twi);

    const int img = blockIdx.x / TILES;
    const int w0  = (blockIdx.x % TILES) * TT;
    const int ch  = img % NCH;
    float2* sp = g_spec + (size_t)img*HW + w0;
    const float* ab = g_ampsum + (size_t)ch*HW + w0;
    const float* rb = running + (size_t)ch*HW + w0;
    const float rs = g_rsum[0];
    for (int idx = threadIdx.x; idx < TT*NFFT; idx += BLOCK) {
        const int c = idx & (TT-1), h = idx >> 4;
        float2 v = sp[(size_t)h*NFFT + c];
        const float mean = ab[h*NFFT + c] * (1.0f/32.0f);
        const float na = (rs == 0.0f) ? mean : (0.9f*rb[h*NFFT + c] + 0.1f*mean);
        const float amp = sqrtf(v.x*v.x + v.y*v.y);
        float orr, oii;
        if (amp > 0.0f) { const float sc = na/amp; orr = v.x*sc; oii = v.y*sc; }
        else            { orr = na; oii = 0.0f; }
        reA[h*ES + c] = orr; imA[h*ES + c] = oii;
    }
    __syncthreads();
    fft384_tile<-1>(reA, imA, reB, imB, twr, twi);
    for (int idx = threadIdx.x; idx < TT*NFFT; idx += BLOCK) {
        const int c = idx & (TT-1), h = idx >> 4;
        sp[(size_t)h*NFFT + c] = make_float2(reB[h*ES + c], imB[h*ES + c]);
    }
}

__global__ void __launch_bounds__(BLOCK) k_row_inv(float* __restrict__ out)
{
    extern __shared__ float sm[];
    float* reA = sm;         float* imA = sm + BUF;
    float* reB = sm + 2*BUF; float* imB = sm + 3*BUF;
    float* twr = sm + 4*BUF; float* twi = twr + NFFT;
    build_tw<-1>(twr, twi);

    const int img = blockIdx.x / TILES;
    const int h0  = (blockIdx.x % TILES) * TT;
    const float2* sp = g_spec + (size_t)img*HW + (size_t)h0*NFFT;
    for (int idx = threadIdx.x; idx < TT*NFFT; idx += BLOCK) {
        const int w = idx % NFFT, r = idx / NFFT;
        float2 v = sp[idx];
        reA[w*ES + r] = v.x; imA[w*ES + r] = v.y;
    }
    __syncthreads();
    fft384_tile<-1>(reA, imA, reB, imB, twr, twi);
    float* op = out + (size_t)img*HW + (size_t)h0*NFFT;
    const float inv = 1.0f/147456.0f;   // 1/(384*384), full ifft2 normalization
    for (int idx = threadIdx.x; idx < TT*NFFT; idx += BLOCK) {
        const int w = idx % NFFT, r = idx / NFFT;
        op[idx] = reB[w*ES + r] * inv;
    }
}

// ---------------- launch ----------------
extern "C" void kernel_launch(void* const* d_in, const int* in_sizes, int n_in,
                              void* d_out, int out_size)
{
    const float* x       = (const float*)d_in[0];
    const float* running = (const float*)d_in[1];
    float* out = (float*)d_out;

    void* p_amp = nullptr; cudaGetSymbolAddress(&p_amp, g_ampsum);
    void* p_rs  = nullptr; cudaGetSymbolAddress(&p_rs,  g_rsum);

    cudaFuncSetAttribute(k_row_fwd, cudaFuncAttributeMaxDynamicSharedMemorySize, SMEM_BYTES);
    cudaFuncSetAttribute(k_col_fwd, cudaFuncAttributeMaxDynamicSharedMemorySize, SMEM_BYTES);
    cudaFuncSetAttribute(k_col_inv, cudaFuncAttributeMaxDynamicSharedMemorySize, SMEM_BYTES);
    cudaFuncSetAttribute(k_row_inv, cudaFuncAttributeMaxDynamicSharedMemorySize, SMEM_BYTES);

    cudaMemsetAsync(p_amp, 0, (size_t)NCH*HW*sizeof(float));
    cudaMemsetAsync(p_rs,  0, sizeof(float));

    k_reduce<<<432, BLOCK>>>(running, NCH*HW);

    const int grid = NIMG * TILES;   // 2304
    k_row_fwd<<<grid, BLOCK, SMEM_BYTES>>>(x);
    k_col_fwd<<<grid, BLOCK, SMEM_BYTES>>>();
    k_col_inv<<<grid, BLOCK, SMEM_BYTES>>>(running);
    k_row_inv<<<grid, BLOCK, SMEM_BYTES>>>(out);
}

// round 2
// speedup vs baseline: 1.1325x; 1.1325x over previous
#include <cuda_runtime.h>
#include <math.h>

#define NFFT   384
#define TT     16              // transforms per block
#define ES     17              // padded element stride (floats) to dodge bank conflicts
#define HW     147456          // 384*384
#define NIMG   96              // 32 batch * 3 channels
#define NPIX   (NIMG*HW)
#define NCH    3
#define BLOCK  768             // 1 butterfly/thread on radix-8 stages
#define RBLOCK 256
#define TILES  (NFFT/TT)       // 24
#define BUF    (NFFT*ES)       // 6528 floats per smem plane
#define SMEM_FLOATS (4*BUF + 2*NFFT)
#define SMEM_BYTES  (SMEM_FLOATS*4)
#define TWO_PI 6.283185307179586476925286766559

// ---------------- device scratch (no allocation allowed) ----------------
__device__ float2 g_spec[NPIX];        // 113 MB complex spectrum scratch
__device__ float  g_ampsum[NCH*HW];    // batch-summed amplitude
__device__ float  g_rsum[1];           // sum(running_amp) flag

// ---------------- butterflies ----------------
// S = +1 : exp(-i theta) (forward).  S = -1 : exp(+i theta) (inverse).
__device__ __forceinline__ void bfly8(float S,
    const float ar[8], const float ai[8], float br[8], float bi[8])
{
    const float c = 0.70710678118654752440f;
    // E = DFT4(a0,a2,a4,a6)
    float t0r=ar[0]+ar[4], t0i=ai[0]+ai[4];
    float t1r=ar[0]-ar[4], t1i=ai[0]-ai[4];
    float t2r=ar[2]+ar[6], t2i=ai[2]+ai[6];
    float t3r=ar[2]-ar[6], t3i=ai[2]-ai[6];
    float E0r=t0r+t2r, E0i=t0i+t2i;
    float E2r=t0r-t2r, E2i=t0i-t2i;
    float E1r=t1r+S*t3i, E1i=t1i-S*t3r;
    float E3r=t1r-S*t3i, E3i=t1i+S*t3r;
    // O = DFT4(a1,a3,a5,a7)
    float u0r=ar[1]+ar[5], u0i=ai[1]+ai[5];
    float u1r=ar[1]-ar[5], u1i=ai[1]-ai[5];
    float u2r=ar[3]+ar[7], u2i=ai[3]+ai[7];
    float u3r=ar[3]-ar[7], u3i=ai[3]-ai[7];
    float O0r=u0r+u2r, O0i=u0i+u2i;
    float O2r=u0r-u2r, O2i=u0i-u2i;
    float O1r=u1r+S*u3i, O1i=u1i-S*u3r;
    float O3r=u1r-S*u3i, O3i=u1i+S*u3r;
    // O1 *= W8^1 = c(1 - iS) ; O2 *= W8^2 = -iS ; O3 *= W8^3 = -c(1 + iS)
    float w1r =  c*(O1r + S*O1i), w1i =  c*(O1i - S*O1r);
    float w2r =  S*O2i,           w2i = -S*O2r;
    float w3r = -c*(O3r - S*O3i), w3i = -c*(O3i + S*O3r);
    br[0]=E0r+O0r; bi[0]=E0i+O0i;
    br[4]=E0r-O0r; bi[4]=E0i-O0i;
    br[1]=E1r+w1r; bi[1]=E1i+w1i;
    br[5]=E1r-w1r; bi[5]=E1i-w1i;
    br[2]=E2r+w2r; bi[2]=E2i+w2i;
    br[6]=E2r-w2r; bi[6]=E2i-w2i;
    br[3]=E3r+w3r; bi[3]=E3i+w3i;
    br[7]=E3r-w3r; bi[7]=E3i-w3i;
}

__device__ __forceinline__ void bfly6(float S,
    const float ar[6], const float ai[6], float br[6], float bi[6])
{
    const float s3 = 0.86602540378443864676f;
    // E = DFT3(a0,a2,a4)
    float t1r=ar[2]+ar[4], t1i=ai[2]+ai[4];
    float E0r=ar[0]+t1r,   E0i=ai[0]+t1i;
    float t2r=ar[0]-0.5f*t1r, t2i=ai[0]-0.5f*t1i;
    float t3r=s3*(ar[2]-ar[4]), t3i=s3*(ai[2]-ai[4]);
    float E1r=t2r+S*t3i, E1i=t2i-S*t3r;
    float E2r=t2r-S*t3i, E2i=t2i+S*t3r;
    // O = DFT3(a1,a3,a5)
    float v1r=ar[3]+ar[5], v1i=ai[3]+ai[5];
    float O0r=ar[1]+v1r,   O0i=ai[1]+v1i;
    float v2r=ar[1]-0.5f*v1r, v2i=ai[1]-0.5f*v1i;
    float v3r=s3*(ar[3]-ar[5]), v3i=s3*(ai[3]-ai[5]);
    float O1r=v2r+S*v3i, O1i=v2i-S*v3r;
    float O2r=v2r-S*v3i, O2i=v2i+S*v3r;
    // O1 *= W6^1 = 0.5 - iS*s3 ; O2 *= W6^2 = -0.5 - iS*s3
    float w1r =  0.5f*O1r + S*s3*O1i, w1i =  0.5f*O1i - S*s3*O1r;
    float w2r = -0.5f*O2r + S*s3*O2i, w2i = -0.5f*O2i - S*s3*O2r;
    br[0]=E0r+O0r; bi[0]=E0i+O0i;
    br[3]=E0r-O0r; bi[3]=E0i-O0i;
    br[1]=E1r+w1r; bi[1]=E1i+w1i;
    br[4]=E1r-w1r; bi[4]=E1i-w1i;
    br[2]=E2r+w2r; bi[2]=E2i+w2i;
    br[5]=E2r-w2r; bi[5]=E2i-w2i;
}

// ---------------- twiddle table : tw[k] = exp(-i*SGN*2*pi*k/384) ----------------
template<int SGN>
__device__ __forceinline__ void build_tw(float* twr, float* twi)
{
    for (int k = threadIdx.x; k < NFFT; k += BLOCK) {
        float sv, cv;
        sincosf((float)k * (float)(TWO_PI/384.0), &sv, &cv);
        twr[k] = cv;
        twi[k] = (SGN > 0) ? -sv : sv;
    }
}

// ---------------- 384-pt Stockham FFT, radices [8,8,6], 16 transforms/block ----------------
// Input in (reA,imA); output in natural order in (reB,imB).
template<int SGN>
__device__ __forceinline__ void fft384_tile(
    float* reA, float* imA, float* reB, float* imB,
    const float* __restrict__ twr, const float* __restrict__ twi)
{
    constexpr float S = (float)SGN;
    // ---- Stage 1: radix-8, s=1, A -> B ----  (768 items: 1/thread)
    for (int i = threadIdx.x; i < TT*48; i += BLOCK) {
        const int t = i & (TT-1);
        const int p = i >> 4;                 // 0..47
        float ar[8], ai[8], br[8], bi[8];
#pragma unroll
        for (int j = 0; j < 8; ++j) {
            const int e = p + 48*j;
            ar[j] = reA[e*ES + t]; ai[j] = imA[e*ES + t];
        }
        bfly8(S, ar, ai, br, bi);
#pragma unroll
        for (int j = 1; j < 8; ++j) {
            const int w = p*j;
            const float cr = twr[w], ci = twi[w];
            const float xr = br[j], xi = bi[j];
            br[j] = xr*cr - xi*ci;
            bi[j] = xr*ci + xi*cr;
        }
#pragma unroll
        for (int j = 0; j < 8; ++j) {
            const int e = 8*p + j;
            reB[e*ES + t] = br[j]; imB[e*ES + t] = bi[j];
        }
    }
    __syncthreads();
    // ---- Stage 2: radix-8, s=8, B -> A ----  (768 items: 1/thread)
    for (int i = threadIdx.x; i < TT*48; i += BLOCK) {
        const int t = i & (TT-1);
        const int u = i >> 4;                 // 0..47
        const int q = u & 7;
        const int p = u >> 3;                 // 0..5
        const int base = q + 8*p;
        float ar[8], ai[8], br[8], bi[8];
#pragma unroll
        for (int j = 0; j < 8; ++j) {
            const int e = base + 48*j;
            ar[j] = reB[e*ES + t]; ai[j] = imB[e*ES + t];
        }
        bfly8(S, ar, ai, br, bi);
#pragma unroll
        for (int j = 1; j < 8; ++j) {
            const int w = 8*p*j;
            const float cr = twr[w], ci = twi[w];
            const float xr = br[j], xi = bi[j];
            br[j] = xr*cr - xi*ci;
            bi[j] = xr*ci + xi*cr;
        }
#pragma unroll
        for (int j = 0; j < 8; ++j) {
            const int e = q + 64*p + 8*j;
            reA[e*ES + t] = br[j]; imA[e*ES + t] = bi[j];
        }
    }
    __syncthreads();
    // ---- Stage 3: radix-6, s=64, A -> B (all twiddles = 1) ---- (1024 items)
    for (int i = threadIdx.x; i < TT*64; i += BLOCK) {
        const int t = i & (TT-1);
        const int q = i >> 4;                 // 0..63
        float ar[6], ai[6], br[6], bi[6];
#pragma unroll
        for (int j = 0; j < 6; ++j) {
            const int e = q + 64*j;
            ar[j] = reA[e*ES + t]; ai[j] = imA[e*ES + t];
        }
        bfly6(S, ar, ai, br, bi);
#pragma unroll
        for (int j = 0; j < 6; ++j) {
            const int e = q + 64*j;
            reB[e*ES + t] = br[j]; imB[e*ES + t] = bi[j];
        }
    }
    __syncthreads();
}

// ---------------- kernels ----------------
__global__ void __launch_bounds__(RBLOCK) k_reduce(const float* __restrict__ a, int n)
{
    float s = 0.f;
    for (int i = blockIdx.x*RBLOCK + threadIdx.x; i < n; i += gridDim.x*RBLOCK)
        s += a[i];
#pragma unroll
    for (int o = 16; o > 0; o >>= 1) s += __shfl_down_sync(0xffffffffu, s, o);
    __shared__ float ws[RBLOCK/32];
    if ((threadIdx.x & 31) == 0) ws[threadIdx.x >> 5] = s;
    __syncthreads();
    if (threadIdx.x < RBLOCK/32) {
        s = ws[threadIdx.x];
#pragma unroll
        for (int o = RBLOCK/64; o > 0; o >>= 1) s += __shfl_down_sync(0xffu, s, o);
        if (threadIdx.x == 0) atomicAdd(g_rsum, s);
    }
}

__global__ void __launch_bounds__(BLOCK, 2) k_row_fwd(const float* __restrict__ x)
{
    extern __shared__ float sm[];
    float* reA = sm;         float* imA = sm + BUF;
    float* reB = sm + 2*BUF; float* imB = sm + 3*BUF;
    float* twr = sm + 4*BUF; float* twi = twr + NFFT;
    build_tw<1>(twr, twi);

    const int img = blockIdx.x / TILES;
    const int h0  = (blockIdx.x % TILES) * TT;
    const float* xp = x + (size_t)img*HW + (size_t)h0*NFFT;
    for (int idx = threadIdx.x; idx < TT*NFFT; idx += BLOCK) {
        const int w = idx % NFFT, r = idx / NFFT;
        reA[w*ES + r] = xp[idx];
        imA[w*ES + r] = 0.f;
    }
    __syncthreads();
    fft384_tile<1>(reA, imA, reB, imB, twr, twi);
    float2* sp = g_spec + (size_t)img*HW + (size_t)h0*NFFT;
    for (int idx = threadIdx.x; idx < TT*NFFT; idx += BLOCK) {
        const int w = idx % NFFT, r = idx / NFFT;
        sp[idx] = make_float2(reB[w*ES + r], imB[w*ES + r]);
    }
}

__global__ void __launch_bounds__(BLOCK, 2) k_col_fwd()
{
    extern __shared__ float sm[];
    float* reA = sm;         float* imA = sm + BUF;
    float* reB = sm + 2*BUF; float* imB = sm + 3*BUF;
    float* twr = sm + 4*BUF; float* twi = twr + NFFT;
    build_tw<1>(twr, twi);

    const int img = blockIdx.x / TILES;
    const int w0  = (blockIdx.x % TILES) * TT;
    float2* sp = g_spec + (size_t)img*HW + w0;
    for (int idx = threadIdx.x; idx < TT*NFFT; idx += BLOCK) {
        const int c = idx & (TT-1), h = idx >> 4;
        float2 v = sp[(size_t)h*NFFT + c];
        reA[h*ES + c] = v.x; imA[h*ES + c] = v.y;
    }
    __syncthreads();
    fft384_tile<1>(reA, imA, reB, imB, twr, twi);
    const int ch = img % NCH;
    float* ab = g_ampsum + (size_t)ch*HW + w0;
    for (int idx = threadIdx.x; idx < TT*NFFT; idx += BLOCK) {
        const int c = idx & (TT-1), h = idx >> 4;
        const float re = reB[h*ES + c], im = imB[h*ES + c];
        sp[(size_t)h*NFFT + c] = make_float2(re, im);
        atomicAdd(&ab[h*NFFT + c], sqrtf(re*re + im*im));
    }
}

__global__ void __launch_bounds__(BLOCK, 2) k_col_inv(const float* __restrict__ running)
{
    extern __shared__ float sm[];
    float* reA = sm;         float* imA = sm + BUF;
    float* reB = sm + 2*BUF; float* imB = sm + 3*BUF;
    float* twr = sm + 4*BUF; float* twi = twr + NFFT;
    build_tw<-1>(twr, twi);

    const int img = blockIdx.x / TILES;
    const int w0  = (blockIdx.x % TILES) * TT;
    const int ch  = img % NCH;
    float2* sp = g_spec + (size_t)img*HW + w0;
    const float* ab = g_ampsum + (size_t)ch*HW + w0;
    const float* rb = running + (size_t)ch*HW + w0;
    const float rs = g_rsum[0];
    for (int idx = threadIdx.x; idx < TT*NFFT; idx += BLOCK) {
        const int c = idx & (TT-1), h = idx >> 4;
        float2 v = sp[(size_t)h*NFFT + c];
        const float mean = ab[h*NFFT + c] * (1.0f/32.0f);
        const float na = (rs == 0.0f) ? mean : (0.9f*rb[h*NFFT + c] + 0.1f*mean);
        const float amp = sqrtf(v.x*v.x + v.y*v.y);
        float orr, oii;
        if (amp > 0.0f) { const float sc = na/amp; orr = v.x*sc; oii = v.y*sc; }
        else            { orr = na; oii = 0.0f; }
        reA[h*ES + c] = orr; imA[h*ES + c] = oii;
    }
    __syncthreads();
    fft384_tile<-1>(reA, imA, reB, imB, twr, twi);
    for (int idx = threadIdx.x; idx < TT*NFFT; idx += BLOCK) {
        const int c = idx & (TT-1), h = idx >> 4;
        sp[(size_t)h*NFFT + c] = make_float2(reB[h*ES + c], imB[h*ES + c]);
    }
}

__global__ void __launch_bounds__(BLOCK, 2) k_row_inv(float* __restrict__ out)
{
    extern __shared__ float sm[];
    float* reA = sm;         float* imA = sm + BUF;
    float* reB = sm + 2*BUF; float* imB = sm + 3*BUF;
    float* twr = sm + 4*BUF; float* twi = twr + NFFT;
    build_tw<-1>(twr, twi);

    const int img = blockIdx.x / TILES;
    const int h0  = (blockIdx.x % TILES) * TT;
    const float2* sp = g_spec + (size_t)img*HW + (size_t)h0*NFFT;
    for (int idx = threadIdx.x; idx < TT*NFFT; idx += BLOCK) {
        const int w = idx % NFFT, r = idx / NFFT;
        float2 v = sp[idx];
        reA[w*ES + r] = v.x; imA[w*ES + r] = v.y;
    }
    __syncthreads();
    fft384_tile<-1>(reA, imA, reB, imB, twr, twi);
    float* op = out + (size_t)img*HW + (size_t)h0*NFFT;
    const float inv = 1.0f/147456.0f;   // 1/(384*384), full ifft2 normalization
    for (int idx = threadIdx.x; idx < TT*NFFT; idx += BLOCK) {
        const int w = idx % NFFT, r = idx / NFFT;
        op[idx] = reB[w*ES + r] * inv;
    }
}

// ---------------- launch ----------------
extern "C" void kernel_launch(void* const* d_in, const int* in_sizes, int n_in,
                              void* d_out, int out_size)
{
    const float* x       = (const float*)d_in[0];
    const float* running = (const float*)d_in[1];
    float* out = (float*)d_out;

    void* p_amp = nullptr; cudaGetSymbolAddress(&p_amp, g_ampsum);
    void* p_rs  = nullptr; cudaGetSymbolAddress(&p_rs,  g_rsum);

    cudaFuncSetAttribute(k_row_fwd, cudaFuncAttributeMaxDynamicSharedMemorySize, SMEM_BYTES);
    cudaFuncSetAttribute(k_col_fwd, cudaFuncAttributeMaxDynamicSharedMemorySize, SMEM_BYTES);
    cudaFuncSetAttribute(k_col_inv, cudaFuncAttributeMaxDynamicSharedMemorySize, SMEM_BYTES);
    cudaFuncSetAttribute(k_row_inv, cudaFuncAttributeMaxDynamicSharedMemorySize, SMEM_BYTES);

    cudaMemsetAsync(p_amp, 0, (size_t)NCH*HW*sizeof(float));
    cudaMemsetAsync(p_rs,  0, sizeof(float));

    k_reduce<<<432, RBLOCK>>>(running, NCH*HW);

    const int grid = NIMG * TILES;   // 2304
    k_row_fwd<<<grid, BLOCK, SMEM_BYTES>>>(x);
    k_col_fwd<<<grid, BLOCK, SMEM_BYTES>>>();
    k_col_inv<<<grid, BLOCK, SMEM_BYTES>>>(running);
    k_row_inv<<<grid, BLOCK, SMEM_BYTES>>>(out);
}

// round 3
// speedup vs baseline: 2.1742x; 1.9199x over previous
#include <cuda_runtime.h>
#include <math.h>

#define NFFT   384
#define TT     16              // transforms per block
#define ES     17              // padded smem stride
#define HW     147456          // 384*384
#define NIMG   96              // 32 batch * 3 channels
#define NCH    3
#define W193   193             // stored half-spectrum columns
#define SPI    (W193*NFFT)     // 74112 float2 per image
#define BLOCK  768
#define RBLOCK 256
#define BUF    (NFFT*ES)       // 6528 floats per smem plane
#define SMEM_FLOATS (4*BUF + 2*NFFT)
#define SMEM_BYTES  (SMEM_FLOATS*4)
#define ROWTILES 12            // 32 real rows (16 packed FFTs) per block
#define COLTILES 13            // ceil(193/16)
#define TWO_PI 6.283185307179586476925286766559

// ---------------- device scratch ----------------
__device__ float2 g_spec[NIMG*SPI];     // 57 MB half-spectrum, transposed [img][w][h]
__device__ float  g_ampsum[NCH*SPI];    // batch-summed amplitude, transposed
__device__ float  g_runT[NCH*SPI];      // symmetrized+transposed running_amp
__device__ float  g_rsum[1];

// ---------------- butterflies (S=+1 fwd, S=-1 inv) ----------------
__device__ __forceinline__ void bfly8(float S,
    const float ar[8], const float ai[8], float br[8], float bi[8])
{
    const float c = 0.70710678118654752440f;
    float t0r=ar[0]+ar[4], t0i=ai[0]+ai[4];
    float t1r=ar[0]-ar[4], t1i=ai[0]-ai[4];
    float t2r=ar[2]+ar[6], t2i=ai[2]+ai[6];
    float t3r=ar[2]-ar[6], t3i=ai[2]-ai[6];
    float E0r=t0r+t2r, E0i=t0i+t2i;
    float E2r=t0r-t2r, E2i=t0i-t2i;
    float E1r=t1r+S*t3i, E1i=t1i-S*t3r;
    float E3r=t1r-S*t3i, E3i=t1i+S*t3r;
    float u0r=ar[1]+ar[5], u0i=ai[1]+ai[5];
    float u1r=ar[1]-ar[5], u1i=ai[1]-ai[5];
    float u2r=ar[3]+ar[7], u2i=ai[3]+ai[7];
    float u3r=ar[3]-ar[7], u3i=ai[3]-ai[7];
    float O0r=u0r+u2r, O0i=u0i+u2i;
    float O2r=u0r-u2r, O2i=u0i-u2i;
    float O1r=u1r+S*u3i, O1i=u1i-S*u3r;
    float O3r=u1r-S*u3i, O3i=u1i+S*u3r;
    float w1r =  c*(O1r + S*O1i), w1i =  c*(O1i - S*O1r);
    float w2r =  S*O2i,           w2i = -S*O2r;
    float w3r = -c*(O3r - S*O3i), w3i = -c*(O3i + S*O3r);
    br[0]=E0r+O0r; bi[0]=E0i+O0i;
    br[4]=E0r-O0r; bi[4]=E0i-O0i;
    br[1]=E1r+w1r; bi[1]=E1i+w1i;
    br[5]=E1r-w1r; bi[5]=E1i-w1i;
    br[2]=E2r+w2r; bi[2]=E2i+w2i;
    br[6]=E2r-w2r; bi[6]=E2i-w2i;
    br[3]=E3r+w3r; bi[3]=E3i+w3i;
    br[7]=E3r-w3r; bi[7]=E3i-w3i;
}

__device__ __forceinline__ void bfly6(float S,
    const float ar[6], const float ai[6], float br[6], float bi[6])
{
    const float s3 = 0.86602540378443864676f;
    float t1r=ar[2]+ar[4], t1i=ai[2]+ai[4];
    float E0r=ar[0]+t1r,   E0i=ai[0]+t1i;
    float t2r=ar[0]-0.5f*t1r, t2i=ai[0]-0.5f*t1i;
    float t3r=s3*(ar[2]-ar[4]), t3i=s3*(ai[2]-ai[4]);
    float E1r=t2r+S*t3i, E1i=t2i-S*t3r;
    float E2r=t2r-S*t3i, E2i=t2i+S*t3r;
    float v1r=ar[3]+ar[5], v1i=ai[3]+ai[5];
    float O0r=ar[1]+v1r,   O0i=ai[1]+v1i;
    float v2r=ar[1]-0.5f*v1r, v2i=ai[1]-0.5f*v1i;
    float v3r=s3*(ar[3]-ar[5]), v3i=s3*(ai[3]-ai[5]);
    float O1r=v2r+S*v3i, O1i=v2i-S*v3r;
    float O2r=v2r-S*v3i, O2i=v2i+S*v3r;
    float w1r =  0.5f*O1r + S*s3*O1i, w1i =  0.5f*O1i - S*s3*O1r;
    float w2r = -0.5f*O2r + S*s3*O2i, w2i = -0.5f*O2i - S*s3*O2r;
    br[0]=E0r+O0r; bi[0]=E0i+O0i;
    br[3]=E0r-O0r; bi[3]=E0i-O0i;
    br[1]=E1r+w1r; bi[1]=E1i+w1i;
    br[4]=E1r-w1r; bi[4]=E1i-w1i;
    br[2]=E2r+w2r; bi[2]=E2i+w2i;
    br[5]=E2r-w2r; bi[5]=E2i-w2i;
}

template<int SGN>
__device__ __forceinline__ void build_tw(float* twr, float* twi)
{
    for (int k = threadIdx.x; k < NFFT; k += BLOCK) {
        float sv, cv;
        sincosf((float)k * (float)(TWO_PI/384.0), &sv, &cv);
        twr[k] = cv;
        twi[k] = (SGN > 0) ? -sv : sv;
    }
}

// 384-pt Stockham FFT, radices [8,8,6], 16 transforms/block; in A, out B (natural order)
template<int SGN>
__device__ __forceinline__ void fft384_tile(
    float* reA, float* imA, float* reB, float* imB,
    const float* __restrict__ twr, const float* __restrict__ twi)
{
    constexpr float S = (float)SGN;
    for (int i = threadIdx.x; i < TT*48; i += BLOCK) {   // radix-8, s=1, A->B
        const int t = i & (TT-1);
        const int p = i >> 4;
        float ar[8], ai[8], br[8], bi[8];
#pragma unroll
        for (int j = 0; j < 8; ++j) {
            const int e = p + 48*j;
            ar[j] = reA[e*ES + t]; ai[j] = imA[e*ES + t];
        }
        bfly8(S, ar, ai, br, bi);
#pragma unroll
        for (int j = 1; j < 8; ++j) {
            const int w = p*j;
            const float cr = twr[w], ci = twi[w];
            const float xr = br[j], xi = bi[j];
            br[j] = xr*cr - xi*ci;
            bi[j] = xr*ci + xi*cr;
        }
#pragma unroll
        for (int j = 0; j < 8; ++j) {
            const int e = 8*p + j;
            reB[e*ES + t] = br[j]; imB[e*ES + t] = bi[j];
        }
    }
    __syncthreads();
    for (int i = threadIdx.x; i < TT*48; i += BLOCK) {   // radix-8, s=8, B->A
        const int t = i & (TT-1);
        const int u = i >> 4;
        const int q = u & 7;
        const int p = u >> 3;
        const int base = q + 8*p;
        float ar[8], ai[8], br[8], bi[8];
#pragma unroll
        for (int j = 0; j < 8; ++j) {
            const int e = base + 48*j;
            ar[j] = reB[e*ES + t]; ai[j] = imB[e*ES + t];
        }
        bfly8(S, ar, ai, br, bi);
#pragma unroll
        for (int j = 1; j < 8; ++j) {
            const int w = 8*p*j;
            const float cr = twr[w], ci = twi[w];
            const float xr = br[j], xi = bi[j];
            br[j] = xr*cr - xi*ci;
            bi[j] = xr*ci + xi*cr;
        }
#pragma unroll
        for (int j = 0; j < 8; ++j) {
            const int e = q + 64*p + 8*j;
            reA[e*ES + t] = br[j]; imA[e*ES + t] = bi[j];
        }
    }
    __syncthreads();
    for (int i = threadIdx.x; i < TT*64; i += BLOCK) {   // radix-6, s=64, A->B
        const int t = i & (TT-1);
        const int q = i >> 4;
        float ar[6], ai[6], br[6], bi[6];
#pragma unroll
        for (int j = 0; j < 6; ++j) {
            const int e = q + 64*j;
            ar[j] = reA[e*ES + t]; ai[j] = imA[e*ES + t];
        }
        bfly6(S, ar, ai, br, bi);
#pragma unroll
        for (int j = 0; j < 6; ++j) {
            const int e = q + 64*j;
            reB[e*ES + t] = br[j]; imB[e*ES + t] = bi[j];
        }
    }
    __syncthreads();
}

// ---------------- small kernels ----------------
__global__ void __launch_bounds__(RBLOCK) k_reduce(const float* __restrict__ a, int n)
{
    float s = 0.f;
    for (int i = blockIdx.x*RBLOCK + threadIdx.x; i < n; i += gridDim.x*RBLOCK)
        s += a[i];
#pragma unroll
    for (int o = 16; o > 0; o >>= 1) s += __shfl_down_sync(0xffffffffu, s, o);
    __shared__ float ws[RBLOCK/32];
    if ((threadIdx.x & 31) == 0) ws[threadIdx.x >> 5] = s;
    __syncthreads();
    if (threadIdx.x < RBLOCK/32) {
        s = ws[threadIdx.x];
#pragma unroll
        for (int o = RBLOCK/64; o > 0; o >>= 1) s += __shfl_down_sync(0xffu, s, o);
        if (threadIdx.x == 0) atomicAdd(g_rsum, s);
    }
}

// symmetrized + transposed running_amp: runT[ch][w*384+h] = (run[h,w]+run[-h,-w])/2
__global__ void __launch_bounds__(RBLOCK) k_symT(const float* __restrict__ running)
{
    int idx = blockIdx.x*RBLOCK + threadIdx.x;
    if (idx >= NCH*SPI) return;
    const int ch = idx / SPI;
    const int rem = idx - ch*SPI;
    const int w = rem / NFFT;
    const int h = rem - w*NFFT;
    const int hm = (NFFT - h) % NFFT;
    const int wm = (NFFT - w) % NFFT;
    const float a = running[ch*HW + h*NFFT + w];
    const float b = running[ch*HW + hm*NFFT + wm];
    g_runT[idx] = 0.5f*(a + b);
}

// ---------------- K1: packed row FFT (2 real rows / complex FFT), store half, transposed ----
__global__ void __launch_bounds__(BLOCK, 2) k_row_fwd(const float* __restrict__ x)
{
    extern __shared__ float sm[];
    float* reA = sm;         float* imA = sm + BUF;
    float* reB = sm + 2*BUF; float* imB = sm + 3*BUF;
    float* twr = sm + 4*BUF; float* twi = twr + NFFT;
    build_tw<1>(twr, twi);

    const int img = blockIdx.x / ROWTILES;
    const int h0  = (blockIdx.x % ROWTILES) * 32;
    const float* xp = x + (size_t)img*HW + (size_t)h0*NFFT;
    for (int idx = threadIdx.x; idx < 32*NFFT; idx += BLOCK) {
        const int r = idx / NFFT, w = idx - r*NFFT;
        const int t = r >> 1;
        const float v = xp[idx];
        if (r & 1) imA[w*ES + t] = v;
        else       reA[w*ES + t] = v;
    }
    __syncthreads();
    fft384_tile<1>(reA, imA, reB, imB, twr, twi);

    float2* sp = g_spec + (size_t)img*SPI;
    for (int i = threadIdx.x; i < TT*W193; i += BLOCK) {
        const int t = i & (TT-1);
        const int w = i >> 4;
        const int wm = (NFFT - w) & (NFFT - 1) ? (NFFT - w) % NFFT : 0; // (384-w)%384
        const float p  = reB[w*ES + t],  q  = imB[w*ES + t];
        const float r_ = reB[wm*ES + t], s_ = imB[wm*ES + t];
        float4 o;
        o.x = 0.5f*(p + r_);  o.y = 0.5f*(q - s_);   // F_even
        o.z = 0.5f*(q + s_);  o.w = 0.5f*(r_ - p);   // F_odd
        *reinterpret_cast<float4*>(sp + (size_t)w*NFFT + h0 + 2*t) = o;
    }
}

// ---------------- K2: column FFT fwd + amplitude accumulate ----------------
__global__ void __launch_bounds__(BLOCK, 2) k_col_fwd()
{
    extern __shared__ float sm[];
    float* reA = sm;         float* imA = sm + BUF;
    float* reB = sm + 2*BUF; float* imB = sm + 3*BUF;
    float* twr = sm + 4*BUF; float* twi = twr + NFFT;
    build_tw<1>(twr, twi);

    const int img = blockIdx.x / COLTILES;
    const int w0  = (blockIdx.x % COLTILES) * TT;
    const int nt  = min(TT, W193 - w0);
    float2* sp = g_spec + (size_t)img*SPI + (size_t)w0*NFFT;
    for (int idx = threadIdx.x; idx < nt*NFFT; idx += BLOCK) {
        const int t = idx / NFFT, h = idx - t*NFFT;
        float2 v = sp[(size_t)t*NFFT + h];
        reA[h*ES + t] = v.x; imA[h*ES + t] = v.y;
    }
    __syncthreads();
    fft384_tile<1>(reA, imA, reB, imB, twr, twi);

    const int ch = img % NCH;
    float* ab = g_ampsum + (size_t)ch*SPI + (size_t)w0*NFFT;
    for (int idx = threadIdx.x; idx < nt*NFFT; idx += BLOCK) {
        const int t = idx / NFFT, h = idx - t*NFFT;
        const float re = reB[h*ES + t], im = imB[h*ES + t];
        sp[(size_t)t*NFFT + h] = make_float2(re, im);
        atomicAdd(&ab[(size_t)t*NFFT + h], sqrtf(re*re + im*im));
    }
}

// ---------------- K3: amplitude swap + column IFFT ----------------
__global__ void __launch_bounds__(BLOCK, 2) k_col_inv()
{
    extern __shared__ float sm[];
    float* reA = sm;         float* imA = sm + BUF;
    float* reB = sm + 2*BUF; float* imB = sm + 3*BUF;
    float* twr = sm + 4*BUF; float* twi = twr + NFFT;
    build_tw<-1>(twr, twi);

    const int img = blockIdx.x / COLTILES;
    const int w0  = (blockIdx.x % COLTILES) * TT;
    const int nt  = min(TT, W193 - w0);
    const int ch  = img % NCH;
    float2* sp = g_spec + (size_t)img*SPI + (size_t)w0*NFFT;
    const float* ab = g_ampsum + (size_t)ch*SPI + (size_t)w0*NFFT;
    const float* rb = g_runT   + (size_t)ch*SPI + (size_t)w0*NFFT;
    const float rs = g_rsum[0];
    for (int idx = threadIdx.x; idx < nt*NFFT; idx += BLOCK) {
        const int t = idx / NFFT, h = idx - t*NFFT;
        float2 v = sp[(size_t)t*NFFT + h];
        const float mean = ab[(size_t)t*NFFT + h] * (1.0f/32.0f);
        const float na = (rs == 0.0f) ? mean : (0.9f*rb[(size_t)t*NFFT + h] + 0.1f*mean);
        const float amp = sqrtf(v.x*v.x + v.y*v.y);
        float orr, oii;
        if (amp > 0.0f) { const float sc = na/amp; orr = v.x*sc; oii = v.y*sc; }
        else            { orr = na; oii = 0.0f; }
        reA[h*ES + t] = orr; imA[h*ES + t] = oii;
    }
    __syncthreads();
    fft384_tile<-1>(reA, imA, reB, imB, twr, twi);
    for (int idx = threadIdx.x; idx < nt*NFFT; idx += BLOCK) {
        const int t = idx / NFFT, h = idx - t*NFFT;
        sp[(size_t)t*NFFT + h] = make_float2(reB[h*ES + t], imB[h*ES + t]);
    }
}

// ---------------- K4: packed row IFFT (C2R, 2 rows / complex IFFT) ----------------
__global__ void __launch_bounds__(BLOCK, 2) k_row_inv(float* __restrict__ out)
{
    extern __shared__ float sm[];
    float* reA = sm;         float* imA = sm + BUF;
    float* reB = sm + 2*BUF; float* imB = sm + 3*BUF;
    float* twr = sm + 4*BUF; float* twi = twr + NFFT;
    build_tw<-1>(twr, twi);

    const int img = blockIdx.x / ROWTILES;
    const int h0  = (blockIdx.x % ROWTILES) * 32;
    const float2* sp = g_spec + (size_t)img*SPI;
    for (int i = threadIdx.x; i < TT*W193; i += BLOCK) {
        const int t = i & (TT-1);
        const int w = i >> 4;
        float4 z = *reinterpret_cast<const float4*>(sp + (size_t)w*NFFT + h0 + 2*t);
        // W[w] = Z_e + i*Z_o ;  W[384-w] = conj(Z_e) + i*conj(Z_o)
        reA[w*ES + t] = z.x - z.w;
        imA[w*ES + t] = z.y + z.z;
        if (w >= 1 && w <= 191) {
            const int e = NFFT - w;
            reA[e*ES + t] = z.x + z.w;
            imA[e*ES + t] = z.z - z.y;
        }
    }
    __syncthreads();
    fft384_tile<-1>(reA, imA, reB, imB, twr, twi);
    float* op = out + (size_t)img*HW + (size_t)h0*NFFT;
    const float inv = 1.0f/147456.0f;
    for (int idx = threadIdx.x; idx < 32*NFFT; idx += BLOCK) {
        const int r = idx / NFFT, w = idx - r*NFFT;
        const int t = r >> 1;
        const float v = (r & 1) ? imB[w*ES + t] : reB[w*ES + t];
        op[idx] = v * inv;
    }
}

// ---------------- launch ----------------
extern "C" void kernel_launch(void* const* d_in, const int* in_sizes, int n_in,
                              void* d_out, int out_size)
{
    const float* x       = (const float*)d_in[0];
    const float* running = (const float*)d_in[1];
    float* out = (float*)d_out;

    void* p_amp = nullptr; cudaGetSymbolAddress(&p_amp, g_ampsum);
    void* p_rs  = nullptr; cudaGetSymbolAddress(&p_rs,  g_rsum);

    cudaFuncSetAttribute(k_row_fwd, cudaFuncAttributeMaxDynamicSharedMemorySize, SMEM_BYTES);
    cudaFuncSetAttribute(k_col_fwd, cudaFuncAttributeMaxDynamicSharedMemorySize, SMEM_BYTES);
    cudaFuncSetAttribute(k_col_inv, cudaFuncAttributeMaxDynamicSharedMemorySize, SMEM_BYTES);
    cudaFuncSetAttribute(k_row_inv, cudaFuncAttributeMaxDynamicSharedMemorySize, SMEM_BYTES);

    cudaMemsetAsync(p_amp, 0, (size_t)NCH*SPI*sizeof(float));
    cudaMemsetAsync(p_rs,  0, sizeof(float));

    k_reduce<<<432, RBLOCK>>>(running, NCH*HW);
    k_symT<<<(NCH*SPI + RBLOCK-1)/RBLOCK, RBLOCK>>>(running);

    k_row_fwd<<<NIMG*ROWTILES, BLOCK, SMEM_BYTES>>>(x);
    k_col_fwd<<<NIMG*COLTILES, BLOCK, SMEM_BYTES>>>();
    k_col_inv<<<NIMG*COLTILES, BLOCK, SMEM_BYTES>>>();
    k_row_inv<<<NIMG*ROWTILES, BLOCK, SMEM_BYTES>>>(out);
}

// round 4
// speedup vs baseline: 2.9028x; 1.3351x over previous
#include <cuda_runtime.h>
#include <math.h>

#define NFFT   384
#define TT     16              // transforms per block
#define ES     17              // padded smem stride (in float2 units)
#define HW     147456          // 384*384
#define NIMG   96              // 32 batch * 3 channels
#define NCH    3
#define W193   193             // stored half-spectrum columns
#define SPI    (W193*NFFT)     // 74112 float2 per image
#define BLOCK  768
#define RBLOCK 256
#define BUF    (NFFT*ES)       // 6528 float2 per complex plane
#define SMEM_F2     (2*BUF + NFFT)
#define SMEM_BYTES  (SMEM_F2*8)
#define ROWTILES 12            // 32 real rows (16 packed FFTs) per block
#define COLTILES 13            // ceil(193/16)
#define TWO_PI 6.283185307179586476925286766559

// ---------------- device scratch ----------------
__device__ float2 g_spec[NIMG*SPI];     // 57 MB half-spectrum, transposed [img][w][h]
__device__ float  g_ampsum[NCH*SPI];    // batch-summed amplitude, transposed
__device__ float  g_runT[NCH*SPI];      // symmetrized+transposed running_amp
__device__ float  g_rsum[1];

// ---------------- complex helpers ----------------
__device__ __forceinline__ float2 cadd(float2 a, float2 b){ return make_float2(a.x+b.x, a.y+b.y); }
__device__ __forceinline__ float2 csub(float2 a, float2 b){ return make_float2(a.x-b.x, a.y-b.y); }
__device__ __forceinline__ float2 cmul(float2 a, float2 b){ return make_float2(a.x*b.x - a.y*b.y, a.x*b.y + a.y*b.x); }
__device__ __forceinline__ float2 cscale(float s, float2 a){ return make_float2(s*a.x, s*a.y); }
// mi(z) = -i*z
__device__ __forceinline__ float2 mi(float2 z){ return make_float2(z.y, -z.x); }

// ---------------- butterflies (S=+1 fwd, S=-1 inv) ----------------
__device__ __forceinline__ void bfly8(float S, const float2 a[8], float2 b[8])
{
    const float c = 0.70710678118654752440f;
    float2 t0 = cadd(a[0], a[4]);
    float2 t1 = csub(a[0], a[4]);
    float2 t2 = cadd(a[2], a[6]);
    float2 t3 = csub(a[2], a[6]);
    float2 E0 = cadd(t0, t2);
    float2 E2 = csub(t0, t2);
    float2 mt3 = cscale(S, mi(t3));
    float2 E1 = cadd(t1, mt3);
    float2 E3 = csub(t1, mt3);
    float2 u0 = cadd(a[1], a[5]);
    float2 u1 = csub(a[1], a[5]);
    float2 u2 = cadd(a[3], a[7]);
    float2 u3 = csub(a[3], a[7]);
    float2 O0 = cadd(u0, u2);
    float2 O2 = csub(u0, u2);
    float2 mu3 = cscale(S, mi(u3));
    float2 O1 = cadd(u1, mu3);
    float2 O3 = csub(u1, mu3);
    float2 w1 = cscale(c,  cadd(O1, cscale(S, mi(O1))));
    float2 w2 = cscale(S,  mi(O2));
    float2 w3 = cscale(-c, csub(O3, cscale(S, mi(O3))));
    b[0] = cadd(E0, O0);  b[4] = csub(E0, O0);
    b[1] = cadd(E1, w1);  b[5] = csub(E1, w1);
    b[2] = cadd(E2, w2);  b[6] = csub(E2, w2);
    b[3] = cadd(E3, w3);  b[7] = csub(E3, w3);
}

__device__ __forceinline__ void bfly6(float S, const float2 a[6], float2 b[6])
{
    const float s3 = 0.86602540378443864676f;
    float2 t1 = cadd(a[2], a[4]);
    float2 E0 = cadd(a[0], t1);
    float2 t2 = csub(a[0], cscale(0.5f, t1));
    float2 t3 = cscale(s3, csub(a[2], a[4]));
    float2 mt3 = cscale(S, mi(t3));
    float2 E1 = cadd(t2, mt3);
    float2 E2 = csub(t2, mt3);
    float2 v1 = cadd(a[3], a[5]);
    float2 O0 = cadd(a[1], v1);
    float2 v2 = csub(a[1], cscale(0.5f, v1));
    float2 v3 = cscale(s3, csub(a[3], a[5]));
    float2 mv3 = cscale(S, mi(v3));
    float2 O1 = cadd(v2, mv3);
    float2 O2 = csub(v2, mv3);
    float2 w1 = cadd(cscale( 0.5f, O1), cscale(S*s3, mi(O1)));
    float2 w2 = cadd(cscale(-0.5f, O2), cscale(S*s3, mi(O2)));
    b[0] = cadd(E0, O0);  b[3] = csub(E0, O0);
    b[1] = cadd(E1, w1);  b[4] = csub(E1, w1);
    b[2] = cadd(E2, w2);  b[5] = csub(E2, w2);
}

template<int SGN>
__device__ __forceinline__ void build_tw(float2* tw)
{
    for (int k = threadIdx.x; k < NFFT; k += BLOCK) {
        float sv, cv;
        sincosf((float)k * (float)(TWO_PI/384.0), &sv, &cv);
        tw[k] = make_float2(cv, (SGN > 0) ? -sv : sv);
    }
}

// 384-pt Stockham FFT, radices [8,8,6], 16 transforms/block; in A, out B (natural order)
template<int SGN>
__device__ __forceinline__ void fft384_tile(float2* A, float2* B, const float2* __restrict__ tw)
{
    constexpr float S = (float)SGN;
    for (int i = threadIdx.x; i < TT*48; i += BLOCK) {   // radix-8, s=1, A->B
        const int t = i & (TT-1);
        const int p = i >> 4;
        float2 a[8], b[8];
#pragma unroll
        for (int j = 0; j < 8; ++j) a[j] = A[(p + 48*j)*ES + t];
        bfly8(S, a, b);
#pragma unroll
        for (int j = 1; j < 8; ++j) b[j] = cmul(b[j], tw[p*j]);
#pragma unroll
        for (int j = 0; j < 8; ++j) B[(8*p + j)*ES + t] = b[j];
    }
    __syncthreads();
    for (int i = threadIdx.x; i < TT*48; i += BLOCK) {   // radix-8, s=8, B->A
        const int t = i & (TT-1);
        const int u = i >> 4;
        const int q = u & 7;
        const int p = u >> 3;
        const int base = q + 8*p;
        float2 a[8], b[8];
#pragma unroll
        for (int j = 0; j < 8; ++j) a[j] = B[(base + 48*j)*ES + t];
        bfly8(S, a, b);
#pragma unroll
        for (int j = 1; j < 8; ++j) b[j] = cmul(b[j], tw[8*p*j]);
#pragma unroll
        for (int j = 0; j < 8; ++j) A[(q + 64*p + 8*j)*ES + t] = b[j];
    }
    __syncthreads();
    for (int i = threadIdx.x; i < TT*64; i += BLOCK) {   // radix-6, s=64, A->B
        const int t = i & (TT-1);
        const int q = i >> 4;
        float2 a[6], b[6];
#pragma unroll
        for (int j = 0; j < 6; ++j) a[j] = A[(q + 64*j)*ES + t];
        bfly6(S, a, b);
#pragma unroll
        for (int j = 0; j < 6; ++j) B[(q + 64*j)*ES + t] = b[j];
    }
    __syncthreads();
}

// ---------------- small kernels ----------------
__global__ void __launch_bounds__(RBLOCK) k_reduce(const float* __restrict__ a, int n)
{
    float s = 0.f;
    for (int i = blockIdx.x*RBLOCK + threadIdx.x; i < n; i += gridDim.x*RBLOCK)
        s += a[i];
#pragma unroll
    for (int o = 16; o > 0; o >>= 1) s += __shfl_down_sync(0xffffffffu, s, o);
    __shared__ float ws[RBLOCK/32];
    if ((threadIdx.x & 31) == 0) ws[threadIdx.x >> 5] = s;
    __syncthreads();
    if (threadIdx.x < RBLOCK/32) {
        s = ws[threadIdx.x];
#pragma unroll
        for (int o = RBLOCK/64; o > 0; o >>= 1) s += __shfl_down_sync(0xffu, s, o);
        if (threadIdx.x == 0) atomicAdd(g_rsum, s);
    }
}

// symmetrized + transposed running_amp: runT[ch][w*384+h] = (run[h,w]+run[-h,-w])/2
__global__ void __launch_bounds__(RBLOCK) k_symT(const float* __restrict__ running)
{
    int idx = blockIdx.x*RBLOCK + threadIdx.x;
    if (idx >= NCH*SPI) return;
    const int ch = idx / SPI;
    const int rem = idx - ch*SPI;
    const int w = rem / NFFT;
    const int h = rem - w*NFFT;
    const int hm = (NFFT - h) % NFFT;
    const int wm = (NFFT - w) % NFFT;
    const float a = running[ch*HW + h*NFFT + w];
    const float b = running[ch*HW + hm*NFFT + wm];
    g_runT[idx] = 0.5f*(a + b);
}

// ---------------- K1: packed row FFT (2 real rows / complex FFT), store half, transposed ----
__global__ void __launch_bounds__(BLOCK, 2) k_row_fwd(const float* __restrict__ x)
{
    extern __shared__ float2 sm[];
    float2* A = sm;  float2* B = sm + BUF;  float2* tw = sm + 2*BUF;
    build_tw<1>(tw);

    const int img = blockIdx.x / ROWTILES;
    const int h0  = (blockIdx.x % ROWTILES) * 32;
    const float* xp = x + (size_t)img*HW + (size_t)h0*NFFT;
    for (int idx = threadIdx.x; idx < TT*NFFT; idx += BLOCK) {
        const int r = idx / NFFT, w = idx - r*NFFT;
        A[w*ES + r] = make_float2(xp[(2*r)*NFFT + w], xp[(2*r+1)*NFFT + w]);
    }
    __syncthreads();
    fft384_tile<1>(A, B, tw);

    float2* sp = g_spec + (size_t)img*SPI;
    for (int i = threadIdx.x; i < TT*W193; i += BLOCK) {
        const int t = i & (TT-1);
        const int w = i >> 4;
        const int wm = w ? NFFT - w : 0;
        const float2 Z  = B[w*ES + t];
        const float2 Zm = B[wm*ES + t];
        float4 o;
        o.x = 0.5f*(Z.x + Zm.x);  o.y = 0.5f*(Z.y - Zm.y);   // F_even
        o.z = 0.5f*(Z.y + Zm.y);  o.w = 0.5f*(Zm.x - Z.x);   // F_odd
        *reinterpret_cast<float4*>(sp + (size_t)w*NFFT + h0 + 2*t) = o;
    }
}

// ---------------- K2: column FFT fwd + amplitude accumulate ----------------
__global__ void __launch_bounds__(BLOCK, 2) k_col_fwd()
{
    extern __shared__ float2 sm[];
    float2* A = sm;  float2* B = sm + BUF;  float2* tw = sm + 2*BUF;
    build_tw<1>(tw);

    const int img = blockIdx.x / COLTILES;
    const int w0  = (blockIdx.x % COLTILES) * TT;
    const int nt  = min(TT, W193 - w0);
    float2* sp = g_spec + (size_t)img*SPI + (size_t)w0*NFFT;
    for (int idx = threadIdx.x; idx < nt*NFFT; idx += BLOCK) {
        const int t = idx / NFFT, h = idx - t*NFFT;
        A[h*ES + t] = sp[(size_t)t*NFFT + h];
    }
    __syncthreads();
    fft384_tile<1>(A, B, tw);

    const int ch = img % NCH;
    float* ab = g_ampsum + (size_t)ch*SPI + (size_t)w0*NFFT;
    for (int idx = threadIdx.x; idx < nt*NFFT; idx += BLOCK) {
        const int t = idx / NFFT, h = idx - t*NFFT;
        const float2 v = B[h*ES + t];
        sp[(size_t)t*NFFT + h] = v;
        atomicAdd(&ab[(size_t)t*NFFT + h], sqrtf(v.x*v.x + v.y*v.y));
    }
}

// ---------------- K3: amplitude swap + column IFFT ----------------
__global__ void __launch_bounds__(BLOCK, 2) k_col_inv()
{
    extern __shared__ float2 sm[];
    float2* A = sm;  float2* B = sm + BUF;  float2* tw = sm + 2*BUF;
    build_tw<-1>(tw);

    const int img = blockIdx.x / COLTILES;
    const int w0  = (blockIdx.x % COLTILES) * TT;
    const int nt  = min(TT, W193 - w0);
    const int ch  = img % NCH;
    float2* sp = g_spec + (size_t)img*SPI + (size_t)w0*NFFT;
    const float* ab = g_ampsum + (size_t)ch*SPI + (size_t)w0*NFFT;
    const float* rb = g_runT   + (size_t)ch*SPI + (size_t)w0*NFFT;
    const float rs = g_rsum[0];
    for (int idx = threadIdx.x; idx < nt*NFFT; idx += BLOCK) {
        const int t = idx / NFFT, h = idx - t*NFFT;
        float2 v = sp[(size_t)t*NFFT + h];
        const float mean = ab[(size_t)t*NFFT + h] * (1.0f/32.0f);
        const float na = (rs == 0.0f) ? mean : (0.9f*rb[(size_t)t*NFFT + h] + 0.1f*mean);
        const float amp = sqrtf(v.x*v.x + v.y*v.y);
        float2 o;
        if (amp > 0.0f) { const float sc = na/amp; o = make_float2(v.x*sc, v.y*sc); }
        else            { o = make_float2(na, 0.0f); }
        A[h*ES + t] = o;
    }
    __syncthreads();
    fft384_tile<-1>(A, B, tw);
    for (int idx = threadIdx.x; idx < nt*NFFT; idx += BLOCK) {
        const int t = idx / NFFT, h = idx - t*NFFT;
        sp[(size_t)t*NFFT + h] = B[h*ES + t];
    }
}

// ---------------- K4: packed row IFFT (C2R, 2 rows / complex IFFT) ----------------
__global__ void __launch_bounds__(BLOCK, 2) k_row_inv(float* __restrict__ out)
{
    extern __shared__ float2 sm[];
    float2* A = sm;  float2* B = sm + BUF;  float2* tw = sm + 2*BUF;
    build_tw<-1>(tw);

    const int img = blockIdx.x / ROWTILES;
    const int h0  = (blockIdx.x % ROWTILES) * 32;
    const float2* sp = g_spec + (size_t)img*SPI;
    for (int i = threadIdx.x; i < TT*W193; i += BLOCK) {
        const int t = i & (TT-1);
        const int w = i >> 4;
        float4 z = *reinterpret_cast<const float4*>(sp + (size_t)w*NFFT + h0 + 2*t);
        // W[w] = Z_e + i*Z_o ;  W[384-w] = conj(Z_e) + i*conj(Z_o)
        A[w*ES + t] = make_float2(z.x - z.w, z.y + z.z);
        if (w >= 1 && w <= 191)
            A[(NFFT - w)*ES + t] = make_float2(z.x + z.w, z.z - z.y);
    }
    __syncthreads();
    fft384_tile<-1>(A, B, tw);
    float* op = out + (size_t)img*HW + (size_t)h0*NFFT;
    const float inv = 1.0f/147456.0f;
    for (int idx = threadIdx.x; idx < 32*NFFT; idx += BLOCK) {
        const int r = idx / NFFT, w = idx - r*NFFT;
        const float2 z = B[w*ES + (r >> 1)];
        op[idx] = ((r & 1) ? z.y : z.x) * inv;
    }
}

// ---------------- launch ----------------
extern "C" void kernel_launch(void* const* d_in, const int* in_sizes, int n_in,
                              void* d_out, int out_size)
{
    const float* x       = (const float*)d_in[0];
    const float* running = (const float*)d_in[1];
    float* out = (float*)d_out;

    void* p_amp = nullptr; cudaGetSymbolAddress(&p_amp, g_ampsum);
    void* p_rs  = nullptr; cudaGetSymbolAddress(&p_rs,  g_rsum);

    cudaFuncSetAttribute(k_row_fwd, cudaFuncAttributeMaxDynamicSharedMemorySize, SMEM_BYTES);
    cudaFuncSetAttribute(k_col_fwd, cudaFuncAttributeMaxDynamicSharedMemorySize, SMEM_BYTES);
    cudaFuncSetAttribute(k_col_inv, cudaFuncAttributeMaxDynamicSharedMemorySize, SMEM_BYTES);
    cudaFuncSetAttribute(k_row_inv, cudaFuncAttributeMaxDynamicSharedMemorySize, SMEM_BYTES);

    cudaMemsetAsync(p_amp, 0, (size_t)NCH*SPI*sizeof(float));
    cudaMemsetAsync(p_rs,  0, sizeof(float));

    k_reduce<<<432, RBLOCK>>>(running, NCH*HW);
    k_symT<<<(NCH*SPI + RBLOCK-1)/RBLOCK, RBLOCK>>>(running);

    k_row_fwd<<<NIMG*ROWTILES, BLOCK, SMEM_BYTES>>>(x);
    k_col_fwd<<<NIMG*COLTILES, BLOCK, SMEM_BYTES>>>();
    k_col_inv<<<NIMG*COLTILES, BLOCK, SMEM_BYTES>>>();
    k_row_inv<<<NIMG*ROWTILES, BLOCK, SMEM_BYTES>>>(out);
}

// round 5
// speedup vs baseline: 3.3957x; 1.1698x over previous
#include <cuda_runtime.h>
#include <math.h>

#define NFFT   384
#define TT     16              // transforms per block
#define ES     17              // padded smem stride (in float2 units)
#define HW     147456          // 384*384
#define NIMG   96              // 32 batch * 3 channels
#define NCH    3
#define W193   193             // stored half-spectrum columns
#define SPI    (W193*NFFT)     // 74112 float2 per image
#define BLOCK  768
#define RBLOCK 256
#define BUF    (NFFT*ES)       // 6528 float2 per complex plane
#define SMEM_F2     (2*BUF + NFFT)
#define SMEM_BYTES  (SMEM_F2*8)
#define ROWTILES 12            // 32 real rows (16 packed FFTs) per block
#define COLTILES 13            // ceil(193/16)
#define TWO_PI 6.283185307179586476925286766559

// ---------------- device scratch ----------------
__device__ float2 g_spec[NIMG*SPI];     // 57 MB half-spectrum, transposed [img][w][h]
__device__ float  g_ampsum[NCH*SPI];    // batch-summed amplitude, transposed
__device__ float  g_runT[NCH*SPI];      // symmetrized+transposed running_amp
__device__ float  g_rsum[1];

// ---------------- complex helpers ----------------
__device__ __forceinline__ float2 cadd(float2 a, float2 b){ return make_float2(a.x+b.x, a.y+b.y); }
__device__ __forceinline__ float2 csub(float2 a, float2 b){ return make_float2(a.x-b.x, a.y-b.y); }
__device__ __forceinline__ float2 cmul(float2 a, float2 b){ return make_float2(a.x*b.x - a.y*b.y, a.x*b.y + a.y*b.x); }
__device__ __forceinline__ float2 cscale(float s, float2 a){ return make_float2(s*a.x, s*a.y); }
// mi(z) = -i*z
__device__ __forceinline__ float2 mi(float2 z){ return make_float2(z.y, -z.x); }

// ---------------- butterflies (S=+1 fwd, S=-1 inv) ----------------
__device__ __forceinline__ void bfly8(float S, const float2 a[8], float2 b[8])
{
    const float c = 0.70710678118654752440f;
    float2 t0 = cadd(a[0], a[4]);
    float2 t1 = csub(a[0], a[4]);
    float2 t2 = cadd(a[2], a[6]);
    float2 t3 = csub(a[2], a[6]);
    float2 E0 = cadd(t0, t2);
    float2 E2 = csub(t0, t2);
    float2 mt3 = cscale(S, mi(t3));
    float2 E1 = cadd(t1, mt3);
    float2 E3 = csub(t1, mt3);
    float2 u0 = cadd(a[1], a[5]);
    float2 u1 = csub(a[1], a[5]);
    float2 u2 = cadd(a[3], a[7]);
    float2 u3 = csub(a[3], a[7]);
    float2 O0 = cadd(u0, u2);
    float2 O2 = csub(u0, u2);
    float2 mu3 = cscale(S, mi(u3));
    float2 O1 = cadd(u1, mu3);
    float2 O3 = csub(u1, mu3);
    float2 w1 = cscale(c,  cadd(O1, cscale(S, mi(O1))));
    float2 w2 = cscale(S,  mi(O2));
    float2 w3 = cscale(-c, csub(O3, cscale(S, mi(O3))));
    b[0] = cadd(E0, O0);  b[4] = csub(E0, O0);
    b[1] = cadd(E1, w1);  b[5] = csub(E1, w1);
    b[2] = cadd(E2, w2);  b[6] = csub(E2, w2);
    b[3] = cadd(E3, w3);  b[7] = csub(E3, w3);
}

__device__ __forceinline__ void bfly6(float S, const float2 a[6], float2 b[6])
{
    const float s3 = 0.86602540378443864676f;
    float2 t1 = cadd(a[2], a[4]);
    float2 E0 = cadd(a[0], t1);
    float2 t2 = csub(a[0], cscale(0.5f, t1));
    float2 t3 = cscale(s3, csub(a[2], a[4]));
    float2 mt3 = cscale(S, mi(t3));
    float2 E1 = cadd(t2, mt3);
    float2 E2 = csub(t2, mt3);
    float2 v1 = cadd(a[3], a[5]);
    float2 O0 = cadd(a[1], v1);
    float2 v2 = csub(a[1], cscale(0.5f, v1));
    float2 v3 = cscale(s3, csub(a[3], a[5]));
    float2 mv3 = cscale(S, mi(v3));
    float2 O1 = cadd(v2, mv3);
    float2 O2 = csub(v2, mv3);
    float2 w1 = cadd(cscale( 0.5f, O1), cscale(S*s3, mi(O1)));
    float2 w2 = cadd(cscale(-0.5f, O2), cscale(S*s3, mi(O2)));
    b[0] = cadd(E0, O0);  b[3] = csub(E0, O0);
    b[1] = cadd(E1, w1);  b[4] = csub(E1, w1);
    b[2] = cadd(E2, w2);  b[5] = csub(E2, w2);
}

template<int SGN>
__device__ __forceinline__ void build_tw(float2* tw)
{
    const int k = threadIdx.x;
    if (k < NFFT) {
        float sv, cv;
        sincosf((float)k * (float)(TWO_PI/384.0), &sv, &cv);
        tw[k] = make_float2(cv, (SGN > 0) ? -sv : sv);
    }
}

// stage-3 radix-6 work item (s=64, tw=1)
template<int SGN>
__device__ __forceinline__ void stage3_item(int i, const float2* A, float2* B)
{
    constexpr float S = (float)SGN;
    const int t = i & (TT-1);
    const int q = i >> 4;
    float2 a[6], b[6];
#pragma unroll
    for (int j = 0; j < 6; ++j) a[j] = A[(q + 64*j)*ES + t];
    bfly6(S, a, b);
#pragma unroll
    for (int j = 0; j < 6; ++j) B[(q + 64*j)*ES + t] = b[j];
}

// 384-pt Stockham FFT, radices [8,8,6], 16 transforms/block, BLOCK=768 exactly.
// In A, out B (natural order).
template<int SGN>
__device__ __forceinline__ void fft384_tile(float2* A, float2* B, const float2* __restrict__ tw)
{
    constexpr float S = (float)SGN;
    {   // ---- stage 1: radix-8, s=1, A->B : exactly 1 item/thread ----
        const int t = threadIdx.x & (TT-1);
        const int p = threadIdx.x >> 4;          // 0..47
        float2 a[8], b[8];
#pragma unroll
        for (int j = 0; j < 8; ++j) a[j] = A[(p + 48*j)*ES + t];
        bfly8(S, a, b);
#pragma unroll
        for (int j = 1; j < 8; ++j) b[j] = cmul(b[j], tw[p*j]);
#pragma unroll
        for (int j = 0; j < 8; ++j) B[(8*p + j)*ES + t] = b[j];
    }
    __syncthreads();
    {   // ---- stage 2: radix-8, s=8, B->A : exactly 1 item/thread ----
        const int t = threadIdx.x & (TT-1);
        const int u = threadIdx.x >> 4;          // 0..47
        const int q = u & 7;
        const int p = u >> 3;                    // 0..5
        const int base = q + 8*p;
        float2 a[8], b[8];
#pragma unroll
        for (int j = 0; j < 8; ++j) a[j] = B[(base + 48*j)*ES + t];
        bfly8(S, a, b);
#pragma unroll
        for (int j = 1; j < 8; ++j) b[j] = cmul(b[j], tw[8*p*j]);
#pragma unroll
        for (int j = 0; j < 8; ++j) A[(q + 64*p + 8*j)*ES + t] = b[j];
    }
    __syncthreads();
    {   // ---- stage 3: radix-6, s=64, A->B : 1024 items = tid and tid+768 ----
        stage3_item<SGN>(threadIdx.x, A, B);
        if (threadIdx.x < TT*64 - BLOCK)         // 256
            stage3_item<SGN>(threadIdx.x + BLOCK, A, B);
    }
    __syncthreads();
}

// ---------------- fused prep: zero ampsum, build symmetrized/transposed runT, reduce rsum ----
__global__ void __launch_bounds__(RBLOCK) k_prep(const float* __restrict__ running)
{
    const int idx = blockIdx.x*RBLOCK + threadIdx.x;
    float s = 0.f;
    if (idx < NCH*SPI) {
        const int ch = idx / SPI;
        const int rem = idx - ch*SPI;
        const int w = rem / NFFT;
        const int h = rem - w*NFFT;
        const int hm = (NFFT - h) % NFFT;
        const int wm = (NFFT - w) % NFFT;
        const float a = running[ch*HW + h*NFFT + w];
        const float b = running[ch*HW + hm*NFFT + wm];
        g_runT[idx]   = 0.5f*(a + b);
        g_ampsum[idx] = 0.f;
        // full-plane sum: direct terms cover w in [0,192]; mirror terms (hm,wm)
        // for w in [1,191] cover columns [193,383], each exactly once.
        s = a + ((w >= 1 && w <= 191) ? b : 0.f);
    }
#pragma unroll
    for (int o = 16; o > 0; o >>= 1) s += __shfl_down_sync(0xffffffffu, s, o);
    __shared__ float ws[RBLOCK/32];
    if ((threadIdx.x & 31) == 0) ws[threadIdx.x >> 5] = s;
    __syncthreads();
    if (threadIdx.x < RBLOCK/32) {
        s = ws[threadIdx.x];
#pragma unroll
        for (int o = RBLOCK/64; o > 0; o >>= 1) s += __shfl_down_sync(0xffu, s, o);
        if (threadIdx.x == 0) atomicAdd(g_rsum, s);
    }
}

// ---------------- K1: packed row FFT (2 real rows / complex FFT), store half, transposed ----
__global__ void __launch_bounds__(BLOCK, 2) k_row_fwd(const float* __restrict__ x)
{
    extern __shared__ float2 sm[];
    float2* A = sm;  float2* B = sm + BUF;  float2* tw = sm + 2*BUF;
    build_tw<1>(tw);

    const int img = blockIdx.x / ROWTILES;
    const int h0  = (blockIdx.x % ROWTILES) * 32;
    const float* xp = x + (size_t)img*HW + (size_t)h0*NFFT;

    const int r0 = threadIdx.x / NFFT;              // 0 or 1
    const int w  = threadIdx.x - r0*NFFT;           // 0..383
    const float* xb = xp + (size_t)(2*r0)*NFFT + w;
#pragma unroll
    for (int k = 0; k < 8; ++k) {                   // r = r0 + 2k
        A[w*ES + (r0 + 2*k)] =
            make_float2(xb[(size_t)(4*k)*NFFT], xb[(size_t)(4*k)*NFFT + NFFT]);
    }
    __syncthreads();
    fft384_tile<1>(A, B, tw);

    float2* sp = g_spec + (size_t)img*SPI;
    for (int i = threadIdx.x; i < TT*W193; i += BLOCK) {
        const int t = i & (TT-1);
        const int ww = i >> 4;
        const int wm = ww ? NFFT - ww : 0;
        const float2 Z  = B[ww*ES + t];
        const float2 Zm = B[wm*ES + t];
        float4 o;
        o.x = 0.5f*(Z.x + Zm.x);  o.y = 0.5f*(Z.y - Zm.y);   // F_even
        o.z = 0.5f*(Z.y + Zm.y);  o.w = 0.5f*(Zm.x - Z.x);   // F_odd
        *reinterpret_cast<float4*>(sp + (size_t)ww*NFFT + h0 + 2*t) = o;
    }
}

// ---------------- K2: column FFT fwd + amplitude accumulate ----------------
__global__ void __launch_bounds__(BLOCK, 2) k_col_fwd()
{
    extern __shared__ float2 sm[];
    float2* A = sm;  float2* B = sm + BUF;  float2* tw = sm + 2*BUF;
    build_tw<1>(tw);

    const int img = blockIdx.x / COLTILES;
    const int w0  = (blockIdx.x % COLTILES) * TT;
    const int nt  = min(TT, W193 - w0);
    float2* sp = g_spec + (size_t)img*SPI + (size_t)w0*NFFT;

    const int t0 = threadIdx.x / NFFT;              // 0 or 1
    const int h  = threadIdx.x - t0*NFFT;           // 0..383
    for (int t = t0; t < nt; t += 2)
        A[h*ES + t] = sp[(size_t)t*NFFT + h];
    __syncthreads();
    fft384_tile<1>(A, B, tw);

    const int ch = img % NCH;
    float* ab = g_ampsum + (size_t)ch*SPI + (size_t)w0*NFFT;
    for (int t = t0; t < nt; t += 2) {
        const float2 v = B[h*ES + t];
        sp[(size_t)t*NFFT + h] = v;
        const float m2 = v.x*v.x + v.y*v.y;
        const float amp = (m2 > 0.f) ? m2*rsqrtf(m2) : 0.f;
        atomicAdd(&ab[(size_t)t*NFFT + h], amp);
    }
}

// ---------------- K3: amplitude swap + column IFFT ----------------
__global__ void __launch_bounds__(BLOCK, 2) k_col_inv()
{
    extern __shared__ float2 sm[];
    float2* A = sm;  float2* B = sm + BUF;  float2* tw = sm + 2*BUF;
    build_tw<-1>(tw);

    const int img = blockIdx.x / COLTILES;
    const int w0  = (blockIdx.x % COLTILES) * TT;
    const int nt  = min(TT, W193 - w0);
    const int ch  = img % NCH;
    float2* sp = g_spec + (size_t)img*SPI + (size_t)w0*NFFT;
    const float* ab = g_ampsum + (size_t)ch*SPI + (size_t)w0*NFFT;
    const float* rb = g_runT   + (size_t)ch*SPI + (size_t)w0*NFFT;
    const float rs = g_rsum[0];

    const int t0 = threadIdx.x / NFFT;
    const int h  = threadIdx.x - t0*NFFT;
    for (int t = t0; t < nt; t += 2) {
        const float2 v = sp[(size_t)t*NFFT + h];
        const float mean = ab[(size_t)t*NFFT + h] * (1.0f/32.0f);
        float na = mean;
        if (rs != 0.0f)                               // uniform branch: skips runT read
            na = 0.9f*rb[(size_t)t*NFFT + h] + 0.1f*mean;
        const float m2 = v.x*v.x + v.y*v.y;
        float2 o;
        if (m2 > 0.0f) { const float sc = na * rsqrtf(m2); o = make_float2(v.x*sc, v.y*sc); }
        else           { o = make_float2(na, 0.0f); }
        A[h*ES + t] = o;
    }
    __syncthreads();
    fft384_tile<-1>(A, B, tw);
    for (int t = t0; t < nt; t += 2)
        sp[(size_t)t*NFFT + h] = B[h*ES + t];
}

// ---------------- K4: packed row IFFT (C2R, 2 rows / complex IFFT) ----------------
__global__ void __launch_bounds__(BLOCK, 2) k_row_inv(float* __restrict__ out)
{
    extern __shared__ float2 sm[];
    float2* A = sm;  float2* B = sm + BUF;  float2* tw = sm + 2*BUF;
    build_tw<-1>(tw);

    const int img = blockIdx.x / ROWTILES;
    const int h0  = (blockIdx.x % ROWTILES) * 32;
    const float2* sp = g_spec + (size_t)img*SPI;
    for (int i = threadIdx.x; i < TT*W193; i += BLOCK) {
        const int t = i & (TT-1);
        const int w = i >> 4;
        float4 z = *reinterpret_cast<const float4*>(sp + (size_t)w*NFFT + h0 + 2*t);
        // W[w] = Z_e + i*Z_o ;  W[384-w] = conj(Z_e) + i*conj(Z_o)
        A[w*ES + t] = make_float2(z.x - z.w, z.y + z.z);
        if (w >= 1 && w <= 191)
            A[(NFFT - w)*ES + t] = make_float2(z.x + z.w, z.z - z.y);
    }
    __syncthreads();
    fft384_tile<-1>(A, B, tw);

    float* op = out + (size_t)img*HW + (size_t)h0*NFFT;
    const float inv = 1.0f/147456.0f;
    const int r0 = threadIdx.x / NFFT;              // output-row parity
    const int w  = threadIdx.x - r0*NFFT;
    float* ob = op + (size_t)r0*NFFT + w;
#pragma unroll
    for (int k = 0; k < 16; ++k) {                  // r = r0 + 2k
        const float2 z = B[w*ES + k];
        ob[(size_t)(2*k)*NFFT] = (r0 ? z.y : z.x) * inv;
    }
}

// ---------------- launch ----------------
extern "C" void kernel_launch(void* const* d_in, const int* in_sizes, int n_in,
                              void* d_out, int out_size)
{
    const float* x       = (const float*)d_in[0];
    const float* running = (const float*)d_in[1];
    float* out = (float*)d_out;

    void* p_rs = nullptr; cudaGetSymbolAddress(&p_rs, g_rsum);

    cudaFuncSetAttribute(k_row_fwd, cudaFuncAttributeMaxDynamicSharedMemorySize, SMEM_BYTES);
    cudaFuncSetAttribute(k_col_fwd, cudaFuncAttributeMaxDynamicSharedMemorySize, SMEM_BYTES);
    cudaFuncSetAttribute(k_col_inv, cudaFuncAttributeMaxDynamicSharedMemorySize, SMEM_BYTES);
    cudaFuncSetAttribute(k_row_inv, cudaFuncAttributeMaxDynamicSharedMemorySize, SMEM_BYTES);

    cudaMemsetAsync(p_rs, 0, sizeof(float));
    k_prep<<<(NCH*SPI + RBLOCK-1)/RBLOCK, RBLOCK>>>(running);

    k_row_fwd<<<NIMG*ROWTILES, BLOCK, SMEM_BYTES>>>(x);
    k_col_fwd<<<NIMG*COLTILES, BLOCK, SMEM_BYTES>>>();
    k_col_inv<<<NIMG*COLTILES, BLOCK, SMEM_BYTES>>>();
    k_row_inv<<<NIMG*ROWTILES, BLOCK, SMEM_BYTES>>>(out);
}